// round 5
// baseline (speedup 1.0000x reference)
#include <cuda_runtime.h>
#include <cuda_bf16.h>

// Table-batched EmbeddingBag forward (SUM pooling).
// T=8 tables, B=8192 batch, D=128 dim, ROWS=200000 rows/table.
// indices: [nnz] int32, offsets: [T*B+1] int32 (ragged bag delimiters,
// features-major), weights: flat [T*ROWS*D] float32.
// out: [B, T*D] float32, batch-major with per-table D blocks concatenated.
//
// One warp per bag. Lane l owns floats [4l, 4l+4) of the D=128 row
// (one float4). Each bag row gather is a fully-coalesced 512B read.

#ifndef EMB_T
#define EMB_T 8
#define EMB_B 8192
#define EMB_D 128
#define EMB_ROWS 200000
#endif

__global__ __launch_bounds__(256) void emb_bag_sum_kernel(
    const int* __restrict__ indices,
    const int* __restrict__ offsets,
    const float4* __restrict__ weights4,   // weights viewed as float4 (32 per row)
    float4* __restrict__ out4,             // out viewed as float4
    int n_bags)
{
    const int warp_id = (blockIdx.x * blockDim.x + threadIdx.x) >> 5;
    const int lane    = threadIdx.x & 31;
    if (warp_id >= n_bags) return;

    const int bag = warp_id;
    const int feature = bag / EMB_B;        // table id
    const int b       = bag - feature * EMB_B;

    const int start = __ldg(offsets + bag);
    const int end   = __ldg(offsets + bag + 1);

    // float4 row stride = D/4 = 32; table base in float4 units
    const long long feat_base = (long long)feature * EMB_ROWS;

    float4 acc = make_float4(0.f, 0.f, 0.f, 0.f);

    #pragma unroll 4
    for (int j = start; j < end; ++j) {
        const int row = __ldg(indices + j);
        const long long grow = feat_base + row;
        float4 v = __ldg(weights4 + grow * (EMB_D / 4) + lane);
        acc.x += v.x; acc.y += v.y; acc.z += v.z; acc.w += v.w;
    }

    // out[b, feature*D + lane*4 .. +4)  -> float4 index
    const long long o = (long long)b * (EMB_T * EMB_D / 4)
                      + feature * (EMB_D / 4) + lane;
    out4[o] = acc;
}

extern "C" void kernel_launch(void* const* d_in, const int* in_sizes, int n_in,
                              void* d_out, int out_size)
{
    const int*   indices = (const int*)d_in[0];
    const int*   offsets = (const int*)d_in[1];
    const float* weights = (const float*)d_in[2];
    float*       out     = (float*)d_out;

    const int n_bags = in_sizes[1] - 1;         // T*B
    const int warps_per_block = 256 / 32;       // 8
    const int blocks = (n_bags + warps_per_block - 1) / warps_per_block;

    emb_bag_sum_kernel<<<blocks, 256>>>(
        indices, offsets,
        (const float4*)weights, (float4*)out, n_bags);
}